// round 4
// baseline (speedup 1.0000x reference)
#include <cuda_runtime.h>
#include <cuda_bf16.h>
#include <mma.h>
#include <math.h>
#include <stdint.h>

using namespace nvcuda;

#define BB 128
#define CC 49
#define NN 3136
#define HH 56

// ---------------- scratch (device globals; no allocations allowed) ----------
__device__ float g_q[BB*CC*CC];                 // q[b][o][p] fp32
__device__ float g_qb[BB*CC];                   // qb[b][c]
__device__ float g_amax_part[BB*14*CC];         // per-chunk maxima
__device__ float g_amax[BB*CC];                 // final max + qb
__device__ float g_spart[4*NN*BB];              // k-split partials of s[m][b]
__device__ __nv_bfloat16 g_vh[BB*NN];           // v hi
__device__ __nv_bfloat16 g_vl[BB*NN];           // v lo
__device__ __nv_bfloat16 g_xth[(size_t)BB*NN*64]; // xT hi: [b][n][j<64]
__device__ __nv_bfloat16 g_xtl[(size_t)BB*NN*64]; // xT lo
__device__ __nv_bfloat16 g_wph[(size_t)NN*NN];  // Wproj hi
__device__ __nv_bfloat16 g_wpl[(size_t)NN*NN];  // Wproj lo
__device__ __nv_bfloat16 g_qwh[BB*64*64];       // qW hi padded [b][c<64][j<64]
__device__ __nv_bfloat16 g_qwl[BB*64*64];       // qW lo padded

__device__ __forceinline__ uint32_t pk2(__nv_bfloat16 a, __nv_bfloat16 b) {
    __nv_bfloat162 t2; t2.x = a; t2.y = b;
    return *reinterpret_cast<uint32_t*>(&t2);
}

// ---------------- kernel 1: v + transposed bf16 split of x ------------------
__global__ void k_v(const float* __restrict__ x) {
    int idx = blockIdx.x * blockDim.x + threadIdx.x;   // over B*N
    int b = idx / NN, n = idx - b * NN;
    const float* xb = x + (size_t)b * CC * NN + n;
    __nv_bfloat16 hv[64], lv[64];
    float s = 0.f;
#pragma unroll
    for (int c = 0; c < CC; c++) {
        float v = xb[c * NN];
        s += v;
        __nv_bfloat16 h = __float2bfloat16(v);
        hv[c] = h;
        lv[c] = __float2bfloat16(v - __bfloat162float(h));
    }
#pragma unroll
    for (int c = CC; c < 64; c++) { hv[c] = __float2bfloat16(0.f); lv[c] = __float2bfloat16(0.f); }
    s *= (1.0f / 49.0f);
    __nv_bfloat16 sh = __float2bfloat16(s);
    g_vh[idx] = sh;
    g_vl[idx] = __float2bfloat16(s - __bfloat162float(sh));
    uint4* dh = (uint4*)g_xth + (size_t)idx * 8;
    uint4* dl = (uint4*)g_xtl + (size_t)idx * 8;
#pragma unroll
    for (int i = 0; i < 8; i++) {
        uint4 u, w;
        u.x = pk2(hv[8*i+0], hv[8*i+1]); u.y = pk2(hv[8*i+2], hv[8*i+3]);
        u.z = pk2(hv[8*i+4], hv[8*i+5]); u.w = pk2(hv[8*i+6], hv[8*i+7]);
        w.x = pk2(lv[8*i+0], lv[8*i+1]); w.y = pk2(lv[8*i+2], lv[8*i+3]);
        w.z = pk2(lv[8*i+4], lv[8*i+5]); w.w = pk2(lv[8*i+6], lv[8*i+7]);
        dh[i] = u; dl[i] = w;
    }
}

// ---------------- kernel 1b: Wproj -> bf16 hi/lo -----------------------------
__global__ void k_wproj(const float* __restrict__ Wproj) {
    size_t e = (size_t)blockIdx.x * blockDim.x + threadIdx.x;  // over NN*NN/8
    const float4* src = (const float4*)Wproj + e * 2;
    float4 a = src[0], c = src[1];
    float f[8] = {a.x, a.y, a.z, a.w, c.x, c.y, c.z, c.w};
    __nv_bfloat16 h[8], l[8];
#pragma unroll
    for (int i = 0; i < 8; i++) {
        h[i] = __float2bfloat16(f[i]);
        l[i] = __float2bfloat16(f[i] - __bfloat162float(h[i]));
    }
    uint4 u, w;
    u.x = pk2(h[0], h[1]); u.y = pk2(h[2], h[3]); u.z = pk2(h[4], h[5]); u.w = pk2(h[6], h[7]);
    w.x = pk2(l[0], l[1]); w.y = pk2(l[2], l[3]); w.z = pk2(l[4], l[5]); w.w = pk2(l[6], l[7]);
    ((uint4*)g_wph)[e] = u;
    ((uint4*)g_wpl)[e] = w;
}

// ---------------- kernel 2: q conv (Conv2d 8x8 stride 8) SIMT ---------------
#define IMG_R 57
#define IMG_S (HH*IMG_R)
#define WQ_OS 65
#define WQ_CS (CC*WQ_OS)
#define QCONV_SMEM ((4*IMG_S + 4*WQ_CS)*4)

__global__ __launch_bounds__(256, 1) void k_qconv(const float* __restrict__ x,
                                                  const float* __restrict__ Wq) {
    extern __shared__ float sm[];
    float* simg = sm;
    float* swq  = sm + 4 * IMG_S;
    int b = blockIdx.x;
    int t = threadIdx.x;
    int tt = t % 49, cs = t / 49;
    int to = tt / 7, tp = tt % 7;
    bool active = (t < 196);

    float acc[49];
#pragma unroll
    for (int i = 0; i < 49; i++) acc[i] = 0.f;
    const float* xb = x + (size_t)b * CC * NN;

    for (int st = 0; st < 13; st++) {
        __syncthreads();
        int cbase = st * 4;
        for (int e = t; e < 4 * NN; e += 256) {
            int chn = e / NN, n = e - chn * NN;
            int h = n / HH, w = n - h * HH;
            int gi = cbase + chn;
            simg[chn * IMG_S + h * IMG_R + w] = (gi < CC) ? xb[gi * NN + n] : 0.f;
        }
        for (int e = t; e < 4 * CC * 64; e += 256) {
            int chn = e / (CC * 64);
            int r = e - chn * (CC * 64);
            int o = r >> 6, k = r & 63;
            int gi = cbase + chn;
            swq[chn * WQ_CS + o * WQ_OS + k] = (gi < CC) ? Wq[o * (CC * 64) + gi * 64 + k] : 0.f;
        }
        __syncthreads();
        if (active) {
            const float* img = simg + cs * IMG_S + (8 * tp) * IMG_R;
            const float* wqc = swq + cs * WQ_CS + (to * 7) * WQ_OS;
#pragma unroll 2
            for (int k = 0; k < 64; k++) {
                int kh = k >> 3, kw = k & 7;
                float iv[7], wv[7];
#pragma unroll
                for (int j = 0; j < 7; j++) iv[j] = img[kh * IMG_R + 8 * j + kw];
#pragma unroll
                for (int a = 0; a < 7; a++) wv[a] = wqc[a * WQ_OS + k];
#pragma unroll
                for (int a = 0; a < 7; a++)
#pragma unroll
                    for (int j = 0; j < 7; j++)
                        acc[a * 7 + j] += wv[a] * iv[j];
            }
        }
    }
    __syncthreads();
    float* sred = sm;
    if (active) {
#pragma unroll
        for (int i = 0; i < 49; i++) sred[(tt * 49 + i) * 4 + cs] = acc[i];
    }
    __syncthreads();
    for (int e = t; e < 2401; e += 256) {
        float s = 0.f;
#pragma unroll
        for (int c4 = 0; c4 < 4; c4++) s += sred[e * 4 + c4];
        int tile = e / 49, w = e - tile * 49;
        int o = (tile / 7) * 7 + (w / 7);
        int p = (tile % 7) * 7 + (w % 7);
        g_q[(b * CC + o) * CC + p] = s;
    }
}

// ---------------- kernel 3: qW = q*Wsr (bf16 split, padded); qb -------------
__global__ void k_qw(const float* __restrict__ Wsr, const float* __restrict__ bsr) {
    __shared__ float sq[CC * CC], sw[CC * CC], sb[CC];
    int b = blockIdx.x, t = threadIdx.x;  // 256 threads
    for (int e = t; e < CC * CC; e += 256) { sq[e] = g_q[b * CC * CC + e]; sw[e] = Wsr[e]; }
    if (t < CC) sb[t] = bsr[t];
    __syncthreads();
    for (int e = t; e < 64 * 64; e += 256) {
        int c = e >> 6, j = e & 63;
        float s = 0.f;
        if (c < CC && j < CC) {
#pragma unroll
            for (int p = 0; p < CC; p++) s += sq[c * CC + p] * sw[p * CC + j];
        }
        __nv_bfloat16 h = __float2bfloat16(s);
        g_qwh[b * 4096 + e] = h;
        g_qwl[b * 4096 + e] = __float2bfloat16(s - __bfloat162float(h));
    }
    if (t < CC) {
        float s = 0.f;
#pragma unroll
        for (int p = 0; p < CC; p++) s += sq[t * CC + p] * sb[p];
        g_qb[b * CC + t] = s;
    }
}

// ---------------- kernel 4: attn max via WMMA bf16 3-seg --------------------
// grid (B, 14). Block: 7 warps. Each warp: 2 n-tiles of 16 cols, 64 rows.
__global__ __launch_bounds__(224) void k_amax_mma() {
    __shared__ float sacc[7 * 64 * 16];
    __shared__ float swr[7][64];
    int b = blockIdx.x, ch = blockIdx.y;
    int t = threadIdx.x, w = t >> 5, lane = t & 31;

    const __nv_bfloat16* Ah = g_qwh + (size_t)b * 4096;
    const __nv_bfloat16* Al = g_qwl + (size_t)b * 4096;
    float rm0 = -INFINITY, rm1 = -INFINITY;

    for (int tile = 0; tile < 2; tile++) {
        int n0 = ch * 224 + (tile * 7 + w) * 16;
        wmma::fragment<wmma::accumulator, 16, 16, 16, float> fc[4];
#pragma unroll
        for (int band = 0; band < 4; band++) wmma::fill_fragment(fc[band], 0.0f);

        const __nv_bfloat16* Bh = g_xth + ((size_t)b * NN + n0) * 64;
        const __nv_bfloat16* Bl = g_xtl + ((size_t)b * NN + n0) * 64;
#pragma unroll
        for (int k = 0; k < 64; k += 16) {
            wmma::fragment<wmma::matrix_b, 16, 16, 16, __nv_bfloat16, wmma::col_major> fbh, fbl;
            wmma::load_matrix_sync(fbh, Bh + k, 64);
            wmma::load_matrix_sync(fbl, Bl + k, 64);
#pragma unroll
            for (int band = 0; band < 4; band++) {
                wmma::fragment<wmma::matrix_a, 16, 16, 16, __nv_bfloat16, wmma::row_major> fah, fal;
                wmma::load_matrix_sync(fah, Ah + band * 16 * 64 + k, 64);
                wmma::load_matrix_sync(fal, Al + band * 16 * 64 + k, 64);
                wmma::mma_sync(fc[band], fah, fbh, fc[band]);
                wmma::mma_sync(fc[band], fal, fbh, fc[band]);
                wmma::mma_sync(fc[band], fah, fbl, fc[band]);
            }
        }
        float* mysm = sacc + w * 1024;
#pragma unroll
        for (int band = 0; band < 4; band++)
            wmma::store_matrix_sync(mysm + band * 256, fc[band], 16, wmma::mem_row_major);
        __syncwarp();
        {
            int r = lane;
            float m = mysm[r * 16];
#pragma unroll
            for (int c = 1; c < 16; c++) m = fmaxf(m, mysm[r * 16 + c]);
            rm0 = fmaxf(rm0, m);
            r = lane + 32;
            m = mysm[r * 16];
#pragma unroll
            for (int c = 1; c < 16; c++) m = fmaxf(m, mysm[r * 16 + c]);
            rm1 = fmaxf(rm1, m);
        }
        __syncwarp();
    }
    swr[w][lane] = rm0;
    swr[w][lane + 32] = rm1;
    __syncthreads();
    if (t < CC) {
        float m = swr[0][t];
#pragma unroll
        for (int w2 = 1; w2 < 7; w2++) m = fmaxf(m, swr[w2][t]);
        g_amax_part[(b * 14 + ch) * CC + t] = m;
    }
}

// ---------------- kernel 4b: final max over 14 chunks + qb ------------------
__global__ void k_amax2() {
    int idx = blockIdx.x * blockDim.x + threadIdx.x;
    if (idx >= BB * CC) return;
    int b = idx / CC, c = idx - b * CC;
    float m = -INFINITY;
#pragma unroll
    for (int ch = 0; ch < 14; ch++) m = fmaxf(m, g_amax_part[(b * 14 + ch) * CC + c]);
    g_amax[idx] = m + g_qb[idx];
}

// ---------------- kernel 5: s[m,b] via WMMA bf16 3-seg, k-split 4 -----------
// grid (49, 4). Block 256 = 8 warps: warp = (band 0..3) x (col-half 0..1).
// Warp tile: 16 m-rows x 64 b-cols; K range 784 per split.
__global__ __launch_bounds__(256) void k_sgemm() {
    int m0 = blockIdx.x * 64, ks = blockIdx.y;
    int t = threadIdx.x, w = t >> 5;
    int band = w & 3, half = w >> 2;
    int k0 = ks * 784;

    wmma::fragment<wmma::accumulator, 16, 16, 16, float> fc[4];
#pragma unroll
    for (int i = 0; i < 4; i++) wmma::fill_fragment(fc[i], 0.0f);

    const __nv_bfloat16* Ahp = g_wph + (size_t)(m0 + band * 16) * NN;
    const __nv_bfloat16* Alp = g_wpl + (size_t)(m0 + band * 16) * NN;

    for (int k = k0; k < k0 + 784; k += 16) {
        wmma::fragment<wmma::matrix_a, 16, 16, 16, __nv_bfloat16, wmma::row_major> fah, fal;
        wmma::load_matrix_sync(fah, Ahp + k, NN);
        wmma::load_matrix_sync(fal, Alp + k, NN);
#pragma unroll
        for (int i = 0; i < 4; i++) {
            int b0 = half * 64 + i * 16;
            wmma::fragment<wmma::matrix_b, 16, 16, 16, __nv_bfloat16, wmma::col_major> fbh, fbl;
            wmma::load_matrix_sync(fbh, g_vh + (size_t)b0 * NN + k, NN);
            wmma::load_matrix_sync(fbl, g_vl + (size_t)b0 * NN + k, NN);
            wmma::mma_sync(fc[i], fah, fbh, fc[i]);
            wmma::mma_sync(fc[i], fal, fbh, fc[i]);
            wmma::mma_sync(fc[i], fah, fbl, fc[i]);
        }
    }
    float* dst = g_spart + (size_t)ks * (NN * BB) + (size_t)(m0 + band * 16) * BB + half * 64;
#pragma unroll
    for (int i = 0; i < 4; i++)
        wmma::store_matrix_sync(dst + i * 16, fc[i], BB, wmma::mem_row_major);
}

// ---------------- kernel 6: out[b,m,c] = amax[b,c] * sum_ks spart[ks][m,b] --
__global__ void k_out(float* __restrict__ out) {
    __shared__ float sa[CC];
    __shared__ float ss[64];
    int b = blockIdx.x, mt = blockIdx.y, t = threadIdx.x;  // 256 threads
    if (t < CC) sa[t] = g_amax[b * CC + t];
    if (t < 64) {
        int m = mt * 64 + t;
        float s = 0.f;
#pragma unroll
        for (int ks = 0; ks < 4; ks++) s += g_spart[(size_t)ks * NN * BB + m * BB + b];
        ss[t] = s;
    }
    __syncthreads();
    float* ob = out + ((size_t)b * NN + mt * 64) * CC;
    for (int e = t; e < 64 * CC; e += 256) {
        int m = e / CC, c = e - m * CC;
        ob[e] = ss[m] * sa[c];
    }
}

// ---------------- launch -----------------------------------------------------
extern "C" void kernel_launch(void* const* d_in, const int* in_sizes, int n_in,
                              void* d_out, int out_size) {
    const float *x = nullptr, *Wq = nullptr, *Wsr = nullptr, *bsr = nullptr, *Wproj = nullptr;
    for (int i = 0; i < n_in; i++) {
        switch (in_sizes[i]) {
            case BB * CC * NN: x     = (const float*)d_in[i]; break;
            case CC * CC * 64: Wq    = (const float*)d_in[i]; break;
            case CC * CC:      Wsr   = (const float*)d_in[i]; break;
            case CC:           bsr   = (const float*)d_in[i]; break;
            case NN * NN:      Wproj = (const float*)d_in[i]; break;
            default: break;
        }
    }
    cudaFuncSetAttribute(k_qconv, cudaFuncAttributeMaxDynamicSharedMemorySize, QCONV_SMEM);

    k_v       <<<(BB * NN) / 256, 256>>>(x);
    k_wproj   <<<(NN * NN / 8) / 256, 256>>>(Wproj);
    k_qconv   <<<BB, 256, QCONV_SMEM>>>(x, Wq);
    k_qw      <<<BB, 256>>>(Wsr, bsr);
    k_amax_mma<<<dim3(BB, 14), 224>>>();
    k_amax2   <<<(BB * CC + 255) / 256, 256>>>();
    k_sgemm   <<<dim3(49, 4), 256>>>();
    k_out     <<<dim3(BB, NN / 64), 256>>>((float*)d_out);
}

// round 5
// speedup vs baseline: 1.0377x; 1.0377x over previous
#include <cuda_runtime.h>
#include <cuda_bf16.h>
#include <mma.h>
#include <math.h>
#include <stdint.h>

using namespace nvcuda;

#define BB 128
#define CC 49
#define NN 3136
#define HH 56

// ---------------- scratch (device globals; no allocations allowed) ----------
__device__ float g_q[BB*CC*CC];                 // q[b][o][p] fp32
__device__ float g_qb[BB*CC];                   // qb[b][c]
__device__ float g_amax_part[BB*14*CC];         // per-chunk maxima
__device__ float g_amax[BB*CC];                 // final max + qb
__device__ float g_spart[7*NN*BB];              // k-split partials of s[m][b]
__device__ __nv_bfloat16 g_vh[BB*NN];           // v hi
__device__ __nv_bfloat16 g_vl[BB*NN];           // v lo
__device__ __nv_bfloat16 g_xh[(size_t)BB*CC*NN];// x hi (native layout)
__device__ __nv_bfloat16 g_xl[(size_t)BB*CC*NN];// x lo
__device__ __nv_bfloat16 g_wph[(size_t)NN*NN];  // Wproj hi
__device__ __nv_bfloat16 g_wpl[(size_t)NN*NN];  // Wproj lo
__device__ __nv_bfloat16 g_qwh[BB*64*64];       // qW hi padded [b][c<64][j<64]
__device__ __nv_bfloat16 g_qwl[BB*64*64];       // qW lo padded

__device__ __forceinline__ uint32_t pk2(__nv_bfloat16 a, __nv_bfloat16 b) {
    __nv_bfloat162 t2; t2.x = a; t2.y = b;
    return *reinterpret_cast<uint32_t*>(&t2);
}

// ---------------- kernel 1: v mean + bf16 hi/lo split of x (native layout) --
__global__ void k_v(const float* __restrict__ x) {
    int idx = blockIdx.x * blockDim.x + threadIdx.x;   // over B*N
    int b = idx / NN, n = idx - b * NN;
    const float* xb = x + (size_t)b * CC * NN + n;
    __nv_bfloat16* xh = g_xh + (size_t)b * CC * NN + n;
    __nv_bfloat16* xl = g_xl + (size_t)b * CC * NN + n;
    float s = 0.f;
#pragma unroll
    for (int c = 0; c < CC; c++) {
        float v = xb[c * NN];
        s += v;
        __nv_bfloat16 h = __float2bfloat16(v);
        xh[c * NN] = h;
        xl[c * NN] = __float2bfloat16(v - __bfloat162float(h));
    }
    s *= (1.0f / 49.0f);
    __nv_bfloat16 sh = __float2bfloat16(s);
    g_vh[idx] = sh;
    g_vl[idx] = __float2bfloat16(s - __bfloat162float(sh));
}

// ---------------- kernel 1b: Wproj -> bf16 hi/lo -----------------------------
__global__ void k_wproj(const float* __restrict__ Wproj) {
    size_t e = (size_t)blockIdx.x * blockDim.x + threadIdx.x;  // over NN*NN/8
    const float4* src = (const float4*)Wproj + e * 2;
    float4 a = src[0], c = src[1];
    float f[8] = {a.x, a.y, a.z, a.w, c.x, c.y, c.z, c.w};
    __nv_bfloat16 h[8], l[8];
#pragma unroll
    for (int i = 0; i < 8; i++) {
        h[i] = __float2bfloat16(f[i]);
        l[i] = __float2bfloat16(f[i] - __bfloat162float(h[i]));
    }
    uint4 u, w;
    u.x = pk2(h[0], h[1]); u.y = pk2(h[2], h[3]); u.z = pk2(h[4], h[5]); u.w = pk2(h[6], h[7]);
    w.x = pk2(l[0], l[1]); w.y = pk2(l[2], l[3]); w.z = pk2(l[4], l[5]); w.w = pk2(l[6], l[7]);
    ((uint4*)g_wph)[e] = u;
    ((uint4*)g_wpl)[e] = w;
}

// ---------------- kernel 2: q conv (Conv2d 8x8 stride 8) SIMT ---------------
#define IMG_R 57
#define IMG_S (HH*IMG_R)
#define WQ_OS 65
#define WQ_CS (CC*WQ_OS)
#define QCONV_SMEM ((4*IMG_S + 4*WQ_CS)*4)

__global__ __launch_bounds__(256, 1) void k_qconv(const float* __restrict__ x,
                                                  const float* __restrict__ Wq) {
    extern __shared__ float sm[];
    float* simg = sm;
    float* swq  = sm + 4 * IMG_S;
    int b = blockIdx.x;
    int t = threadIdx.x;
    int tt = t % 49, cs = t / 49;
    int to = tt / 7, tp = tt % 7;
    bool active = (t < 196);

    float acc[49];
#pragma unroll
    for (int i = 0; i < 49; i++) acc[i] = 0.f;
    const float* xb = x + (size_t)b * CC * NN;

    for (int st = 0; st < 13; st++) {
        __syncthreads();
        int cbase = st * 4;
        for (int e = t; e < 4 * NN; e += 256) {
            int chn = e / NN, n = e - chn * NN;
            int h = n / HH, w = n - h * HH;
            int gi = cbase + chn;
            simg[chn * IMG_S + h * IMG_R + w] = (gi < CC) ? xb[gi * NN + n] : 0.f;
        }
        for (int e = t; e < 4 * CC * 64; e += 256) {
            int chn = e / (CC * 64);
            int r = e - chn * (CC * 64);
            int o = r >> 6, k = r & 63;
            int gi = cbase + chn;
            swq[chn * WQ_CS + o * WQ_OS + k] = (gi < CC) ? Wq[o * (CC * 64) + gi * 64 + k] : 0.f;
        }
        __syncthreads();
        if (active) {
            const float* img = simg + cs * IMG_S + (8 * tp) * IMG_R;
            const float* wqc = swq + cs * WQ_CS + (to * 7) * WQ_OS;
#pragma unroll 2
            for (int k = 0; k < 64; k++) {
                int kh = k >> 3, kw = k & 7;
                float iv[7], wv[7];
#pragma unroll
                for (int j = 0; j < 7; j++) iv[j] = img[kh * IMG_R + 8 * j + kw];
#pragma unroll
                for (int a = 0; a < 7; a++) wv[a] = wqc[a * WQ_OS + k];
#pragma unroll
                for (int a = 0; a < 7; a++)
#pragma unroll
                    for (int j = 0; j < 7; j++)
                        acc[a * 7 + j] += wv[a] * iv[j];
            }
        }
    }
    __syncthreads();
    float* sred = sm;
    if (active) {
#pragma unroll
        for (int i = 0; i < 49; i++) sred[(tt * 49 + i) * 4 + cs] = acc[i];
    }
    __syncthreads();
    for (int e = t; e < 2401; e += 256) {
        float s = 0.f;
#pragma unroll
        for (int c4 = 0; c4 < 4; c4++) s += sred[e * 4 + c4];
        int tile = e / 49, w = e - tile * 49;
        int o = (tile / 7) * 7 + (w / 7);
        int p = (tile % 7) * 7 + (w % 7);
        g_q[(b * CC + o) * CC + p] = s;
    }
}

// ---------------- kernel 3: qW = q*Wsr (bf16 split, padded); qb -------------
__global__ void k_qw(const float* __restrict__ Wsr, const float* __restrict__ bsr) {
    __shared__ float sq[CC * CC], sw[CC * CC], sb[CC];
    int b = blockIdx.x, t = threadIdx.x;  // 256 threads
    for (int e = t; e < CC * CC; e += 256) { sq[e] = g_q[b * CC * CC + e]; sw[e] = Wsr[e]; }
    if (t < CC) sb[t] = bsr[t];
    __syncthreads();
    for (int e = t; e < 64 * 64; e += 256) {
        int c = e >> 6, j = e & 63;
        float s = 0.f;
        if (c < CC && j < CC) {
#pragma unroll
            for (int p = 0; p < CC; p++) s += sq[c * CC + p] * sw[p * CC + j];
        }
        __nv_bfloat16 h = __float2bfloat16(s);
        g_qwh[b * 4096 + e] = h;
        g_qwl[b * 4096 + e] = __float2bfloat16(s - __bfloat162float(h));
    }
    if (t < CC) {
        float s = 0.f;
#pragma unroll
        for (int p = 0; p < CC; p++) s += sq[t * CC + p] * sb[p];
        g_qb[b * CC + t] = s;
    }
}

// ---------------- kernel 4: attn max via WMMA bf16 3-seg, smem-staged -------
// grid (B, 14). 7 warps. A: qW(64x64 padded) smem. B: x[j][n0..n0+223] smem.
// Warp w owns n-tiles w and w+7 (16 cols each), 4 row-bands of 16.
#define AM_ASTR 72
#define AM_BSTR 232
#define AM_AH 0
#define AM_AL (64*AM_ASTR)
#define AM_BH (2*64*AM_ASTR)
#define AM_BL (AM_BH + 64*AM_BSTR)
#define AM_ELEMS (AM_BL + 64*AM_BSTR)
#define AM_SMEM (AM_ELEMS*2)

__global__ __launch_bounds__(224) void k_amax_mma() {
    extern __shared__ __align__(128) __nv_bfloat16 smb[];
    __shared__ float swr[7][64];
    int b = blockIdx.x, ch = blockIdx.y;
    int t = threadIdx.x, w = t >> 5, lane = t & 31;
    int n0 = ch * 224;

    // stage A hi/lo: 64x64 from padded qW, uint2 = 4 bf16
    {
        const uint2* qh = (const uint2*)(g_qwh + (size_t)b * 4096);
        const uint2* ql = (const uint2*)(g_qwl + (size_t)b * 4096);
        for (int e = t; e < 1024; e += 224) {
            int r = e >> 4, c4 = e & 15;
            *(uint2*)&smb[AM_AH + r * AM_ASTR + c4 * 4] = qh[e];
            *(uint2*)&smb[AM_AL + r * AM_ASTR + c4 * 4] = ql[e];
        }
    }
    // stage B hi/lo: 64 rows (j) x 224 cols (n); rows >= 49 zero
    {
        const __nv_bfloat16* xh = g_xh + (size_t)b * CC * NN + n0;
        const __nv_bfloat16* xl = g_xl + (size_t)b * CC * NN + n0;
        uint2 z = make_uint2(0, 0);
        for (int e = t; e < 3584; e += 224) {
            int r = e / 56, c4 = e % 56;
            uint2 vh = z, vl = z;
            if (r < CC) {
                vh = *(const uint2*)(xh + (size_t)r * NN + c4 * 4);
                vl = *(const uint2*)(xl + (size_t)r * NN + c4 * 4);
            }
            *(uint2*)&smb[AM_BH + r * AM_BSTR + c4 * 4] = vh;
            *(uint2*)&smb[AM_BL + r * AM_BSTR + c4 * 4] = vl;
        }
    }
    __syncthreads();

    wmma::fragment<wmma::accumulator, 16, 16, 16, float> fc[2][4];
#pragma unroll
    for (int i = 0; i < 2; i++)
#pragma unroll
        for (int j = 0; j < 4; j++) wmma::fill_fragment(fc[i][j], 0.0f);

#pragma unroll
    for (int tile = 0; tile < 2; tile++) {
        int noff = (tile * 7 + w) * 16;
#pragma unroll
        for (int k = 0; k < 64; k += 16) {
            wmma::fragment<wmma::matrix_b, 16, 16, 16, __nv_bfloat16, wmma::row_major> fbh, fbl;
            wmma::load_matrix_sync(fbh, &smb[AM_BH + k * AM_BSTR + noff], AM_BSTR);
            wmma::load_matrix_sync(fbl, &smb[AM_BL + k * AM_BSTR + noff], AM_BSTR);
#pragma unroll
            for (int band = 0; band < 4; band++) {
                wmma::fragment<wmma::matrix_a, 16, 16, 16, __nv_bfloat16, wmma::row_major> fah, fal;
                wmma::load_matrix_sync(fah, &smb[AM_AH + band * 16 * AM_ASTR + k], AM_ASTR);
                wmma::load_matrix_sync(fal, &smb[AM_AL + band * 16 * AM_ASTR + k], AM_ASTR);
                wmma::mma_sync(fc[tile][band], fah, fbh, fc[tile][band]);
                wmma::mma_sync(fc[tile][band], fal, fbh, fc[tile][band]);
                wmma::mma_sync(fc[tile][band], fah, fbl, fc[tile][band]);
            }
        }
    }
    __syncthreads();   // all MMAs done: safe to reuse B region as reduction scratch

    float* sacc = (float*)&smb[AM_BH] + w * 1024;   // 4KB per warp
    float rm0 = -INFINITY, rm1 = -INFINITY;
#pragma unroll
    for (int tile = 0; tile < 2; tile++) {
#pragma unroll
        for (int band = 0; band < 4; band++)
            wmma::store_matrix_sync(sacc + band * 256, fc[tile][band], 16, wmma::mem_row_major);
        __syncwarp();
        {
            int r = lane;
            float m = sacc[r * 16];
#pragma unroll
            for (int c = 1; c < 16; c++) m = fmaxf(m, sacc[r * 16 + c]);
            rm0 = fmaxf(rm0, m);
            r = lane + 32;
            m = sacc[r * 16];
#pragma unroll
            for (int c = 1; c < 16; c++) m = fmaxf(m, sacc[r * 16 + c]);
            rm1 = fmaxf(rm1, m);
        }
        __syncwarp();
    }
    swr[w][lane] = rm0;
    swr[w][lane + 32] = rm1;
    __syncthreads();
    if (t < CC) {
        float m = swr[0][t];
#pragma unroll
        for (int w2 = 1; w2 < 7; w2++) m = fmaxf(m, swr[w2][t]);
        g_amax_part[(b * 14 + ch) * CC + t] = m;
    }
}

// ---------------- kernel 4b: final max over 14 chunks + qb ------------------
__global__ void k_amax2() {
    int idx = blockIdx.x * blockDim.x + threadIdx.x;
    if (idx >= BB * CC) return;
    int b = idx / CC, c = idx - b * CC;
    float m = -INFINITY;
#pragma unroll
    for (int ch = 0; ch < 14; ch++) m = fmaxf(m, g_amax_part[(b * 14 + ch) * CC + c]);
    g_amax[idx] = m + g_qb[idx];
}

// ---------------- kernel 5: s[m,b] WMMA bf16 3-seg, smem-tiled, k-split 7 ---
// grid (25, 7). Block 256 = 8 warps (4 mw x 2 nw). Tile 128m x 128b, K=448/split.
#define SG_STR 40
__global__ __launch_bounds__(256) void k_sgemm() {
    __shared__ __align__(32) __nv_bfloat16 sAh[128 * SG_STR], sAl[128 * SG_STR];
    __shared__ __align__(32) __nv_bfloat16 sBh[128 * SG_STR], sBl[128 * SG_STR];
    int m0 = blockIdx.x * 128, ks = blockIdx.y;
    int t = threadIdx.x, w = t >> 5;
    int mw = w & 3, nw = w >> 2;

    wmma::fragment<wmma::accumulator, 16, 16, 16, float> fc[2][4];
#pragma unroll
    for (int i = 0; i < 2; i++)
#pragma unroll
        for (int j = 0; j < 4; j++) wmma::fill_fragment(fc[i][j], 0.0f);

    for (int cch = 0; cch < 14; cch++) {
        int kb = ks * 448 + cch * 32;
        __syncthreads();
        uint2 z = make_uint2(0, 0);
        // stage A (Wproj hi/lo): 128 rows x 32 k, uint2 = 4 bf16 (8/row)
        for (int e = t; e < 1024; e += 256) {
            int r = e >> 3, c4 = e & 7;
            int m = m0 + r;
            uint2 vh = z, vl = z;
            if (m < NN) {
                vh = *(const uint2*)(g_wph + (size_t)m * NN + kb + c4 * 4);
                vl = *(const uint2*)(g_wpl + (size_t)m * NN + kb + c4 * 4);
            }
            *(uint2*)&sAh[r * SG_STR + c4 * 4] = vh;
            *(uint2*)&sAl[r * SG_STR + c4 * 4] = vl;
        }
        // stage B (v hi/lo): 128 b-rows x 32 k
        for (int e = t; e < 1024; e += 256) {
            int r = e >> 3, c4 = e & 7;
            *(uint2*)&sBh[r * SG_STR + c4 * 4] = *(const uint2*)(g_vh + (size_t)r * NN + kb + c4 * 4);
            *(uint2*)&sBl[r * SG_STR + c4 * 4] = *(const uint2*)(g_vl + (size_t)r * NN + kb + c4 * 4);
        }
        __syncthreads();
#pragma unroll
        for (int kstep = 0; kstep < 2; kstep++) {
            int k = kstep * 16;
            wmma::fragment<wmma::matrix_b, 16, 16, 16, __nv_bfloat16, wmma::col_major> fbh[4], fbl[4];
#pragma unroll
            for (int j = 0; j < 4; j++) {
                wmma::load_matrix_sync(fbh[j], &sBh[(nw * 64 + j * 16) * SG_STR + k], SG_STR);
                wmma::load_matrix_sync(fbl[j], &sBl[(nw * 64 + j * 16) * SG_STR + k], SG_STR);
            }
#pragma unroll
            for (int i = 0; i < 2; i++) {
                wmma::fragment<wmma::matrix_a, 16, 16, 16, __nv_bfloat16, wmma::row_major> fah, fal;
                wmma::load_matrix_sync(fah, &sAh[(mw * 32 + i * 16) * SG_STR + k], SG_STR);
                wmma::load_matrix_sync(fal, &sAl[(mw * 32 + i * 16) * SG_STR + k], SG_STR);
#pragma unroll
                for (int j = 0; j < 4; j++) {
                    wmma::mma_sync(fc[i][j], fah, fbh[j], fc[i][j]);
                    wmma::mma_sync(fc[i][j], fal, fbh[j], fc[i][j]);
                    wmma::mma_sync(fc[i][j], fah, fbl[j], fc[i][j]);
                }
            }
        }
    }
    float* dst = g_spart + (size_t)ks * (NN * BB);
#pragma unroll
    for (int i = 0; i < 2; i++) {
        int mrow = m0 + mw * 32 + i * 16;
        if (mrow < NN) {
#pragma unroll
            for (int j = 0; j < 4; j++)
                wmma::store_matrix_sync(dst + (size_t)mrow * BB + nw * 64 + j * 16,
                                        fc[i][j], BB, wmma::mem_row_major);
        }
    }
}

// ---------------- kernel 6: out[b,m,c] = amax[b,c] * sum_ks spart[ks][m,b] --
__global__ void k_out(float* __restrict__ out) {
    __shared__ float sa[CC];
    __shared__ float ss[64];
    int b = blockIdx.x, mt = blockIdx.y, t = threadIdx.x;  // 256 threads
    if (t < CC) sa[t] = g_amax[b * CC + t];
    if (t < 64) {
        int m = mt * 64 + t;
        float s = 0.f;
#pragma unroll
        for (int ks = 0; ks < 7; ks++) s += g_spart[(size_t)ks * NN * BB + m * BB + b];
        ss[t] = s;
    }
    __syncthreads();
    float* ob = out + ((size_t)b * NN + mt * 64) * CC;
    for (int e = t; e < 64 * CC; e += 256) {
        int m = e / CC, c = e - m * CC;
        ob[e] = ss[m] * sa[c];
    }
}

// ---------------- launch -----------------------------------------------------
extern "C" void kernel_launch(void* const* d_in, const int* in_sizes, int n_in,
                              void* d_out, int out_size) {
    const float *x = nullptr, *Wq = nullptr, *Wsr = nullptr, *bsr = nullptr, *Wproj = nullptr;
    for (int i = 0; i < n_in; i++) {
        switch (in_sizes[i]) {
            case BB * CC * NN: x     = (const float*)d_in[i]; break;
            case CC * CC * 64: Wq    = (const float*)d_in[i]; break;
            case CC * CC:      Wsr   = (const float*)d_in[i]; break;
            case CC:           bsr   = (const float*)d_in[i]; break;
            case NN * NN:      Wproj = (const float*)d_in[i]; break;
            default: break;
        }
    }
    cudaFuncSetAttribute(k_qconv,    cudaFuncAttributeMaxDynamicSharedMemorySize, QCONV_SMEM);
    cudaFuncSetAttribute(k_amax_mma, cudaFuncAttributeMaxDynamicSharedMemorySize, AM_SMEM);

    k_v       <<<(BB * NN) / 256, 256>>>(x);
    k_wproj   <<<(NN * NN / 8) / 256, 256>>>(Wproj);
    k_qconv   <<<BB, 256, QCONV_SMEM>>>(x, Wq);
    k_qw      <<<BB, 256>>>(Wsr, bsr);
    k_amax_mma<<<dim3(BB, 14), 224, AM_SMEM>>>();
    k_amax2   <<<(BB * CC + 255) / 256, 256>>>();
    k_sgemm   <<<dim3(25, 7), 256>>>();
    k_out     <<<dim3(BB, NN / 64), 256>>>((float*)d_out);
}

// round 8
// speedup vs baseline: 1.2183x; 1.1740x over previous
#include <cuda_runtime.h>
#include <cuda_bf16.h>
#include <mma.h>
#include <math.h>
#include <stdint.h>

using namespace nvcuda;

#define BB 128
#define CC 49
#define NN 3136
#define HH 56

// ---------------- scratch (device globals; no allocations allowed) ----------
__device__ float g_qb[BB*CC];                   // qb[b][c]
__device__ float g_amax_part[BB*14*CC];         // per-chunk maxima
__device__ float g_amax[BB*CC];                 // final max + qb
__device__ float g_spart[7*NN*BB];              // k-split partials of s[m][b]
__device__ __nv_bfloat16 g_vh[BB*NN];           // v hi
__device__ __nv_bfloat16 g_vl[BB*NN];           // v lo
__device__ __nv_bfloat16 g_wqh[64*NN];          // Wq_mat hi [o<64][i*64+k], rows>=49 zero
__device__ __nv_bfloat16 g_wql[64*NN];          // Wq_mat lo
__device__ __nv_bfloat16 g_qwh[BB*64*64];       // qW hi padded [b][c<64][j<64], pad zero
__device__ __nv_bfloat16 g_qwl[BB*64*64];       // qW lo padded

__device__ __forceinline__ uint32_t pk2(__nv_bfloat16 a, __nv_bfloat16 b) {
    __nv_bfloat162 t2; t2.x = a; t2.y = b;
    return *reinterpret_cast<uint32_t*>(&t2);
}
__device__ __forceinline__ void split1(float f, __nv_bfloat16& h, __nv_bfloat16& l) {
    h = __float2bfloat16(f);
    l = __float2bfloat16(f - __bfloat162float(h));
}

// ---------------- kernel A: Wq -> padded bf16 hi/lo matrix ------------------
__global__ void k_wqsplit(const float* __restrict__ Wq) {
    int e = blockIdx.x * blockDim.x + threadIdx.x;   // over 64*3136
    if (e >= 64 * NN) return;
    int r = e / NN, c = e - r * NN;
    float f = (r < CC) ? Wq[r * NN + c] : 0.f;       // Wq is [49][49*64] linear
    __nv_bfloat16 h, l; split1(f, h, l);
    g_wqh[e] = h; g_wql[e] = l;
}

// ---------------- kernel B: q conv as WMMA GEMM + fused qW epilogue ---------
// grid (B). q[64,64] = Wq_mat[64,3136] @ xcol[3136,64]; per-channel K=64 chunks.
// QC_BSTR must be a multiple of 8 (16B) for bf16 wmma loads.
#define QC_ASTR 72
#define QC_BSTR 72
__global__ __launch_bounds__(256) void k_qconv_mma(const float* __restrict__ x,
                                                   const float* __restrict__ Wsr,
                                                   const float* __restrict__ bsr) {
    __shared__ __align__(32) __nv_bfloat16 sA[2 * 64 * QC_ASTR];  // hi | lo
    __shared__ __align__(32) __nv_bfloat16 sB[2 * 64 * QC_BSTR];  // hi | lo
    __nv_bfloat16* sAh = sA; __nv_bfloat16* sAl = sA + 64 * QC_ASTR;
    __nv_bfloat16* sBh = sB; __nv_bfloat16* sBl = sB + 64 * QC_BSTR;
    int b = blockIdx.x, t = threadIdx.x, w = t >> 5;
    int mw = w & 3, nw = w >> 2;      // 4 m-tiles x 2 n-halves(32)

    wmma::fragment<wmma::accumulator, 16, 16, 16, float> fc[2];
    wmma::fill_fragment(fc[0], 0.0f);
    wmma::fill_fragment(fc[1], 0.0f);

    // one-time zero of B (pad columns p in [49,72) stay zero: im2col writes only p<49)
    for (int e = t; e < 2 * 64 * QC_BSTR; e += 256) sB[e] = __float2bfloat16(0.f);

    for (int i = 0; i < CC; i++) {
        __syncthreads();
        // stage B: channel image -> im2col [k=64][p<49], bf16 hi/lo split
        const float* xc = x + ((size_t)b * CC + i) * NN;
        for (int e = t; e < NN; e += 256) {
            int h = e / HH, ww = e - h * HH;
            int k = (h & 7) * 8 + (ww & 7);
            int p = (h >> 3) * 7 + (ww >> 3);
            __nv_bfloat16 hh, ll; split1(xc[e], hh, ll);
            sBh[k * QC_BSTR + p] = hh;
            sBl[k * QC_BSTR + p] = ll;
        }
        // stage A: Wq_mat rows, k-chunk for channel i (uint2 = 4 bf16)
        for (int e = t; e < 1024; e += 256) {
            int r = e >> 4, c4 = e & 15;
            *(uint2*)&sAh[r * QC_ASTR + c4 * 4] = ((const uint2*)g_wqh)[r * 784 + i * 16 + c4];
            *(uint2*)&sAl[r * QC_ASTR + c4 * 4] = ((const uint2*)g_wql)[r * 784 + i * 16 + c4];
        }
        __syncthreads();
#pragma unroll
        for (int k4 = 0; k4 < 4; k4++) {
            wmma::fragment<wmma::matrix_a, 16, 16, 16, __nv_bfloat16, wmma::row_major> fah, fal;
            wmma::load_matrix_sync(fah, &sAh[(mw * 16) * QC_ASTR + k4 * 16], QC_ASTR);
            wmma::load_matrix_sync(fal, &sAl[(mw * 16) * QC_ASTR + k4 * 16], QC_ASTR);
#pragma unroll
            for (int j = 0; j < 2; j++) {
                wmma::fragment<wmma::matrix_b, 16, 16, 16, __nv_bfloat16, wmma::row_major> fbh, fbl;
                wmma::load_matrix_sync(fbh, &sBh[(k4 * 16) * QC_BSTR + nw * 32 + j * 16], QC_BSTR);
                wmma::load_matrix_sync(fbl, &sBl[(k4 * 16) * QC_BSTR + nw * 32 + j * 16], QC_BSTR);
                wmma::mma_sync(fc[j], fah, fbh, fc[j]);
                wmma::mma_sync(fc[j], fal, fbh, fc[j]);
                wmma::mma_sync(fc[j], fah, fbl, fc[j]);
            }
        }
    }
    __syncthreads();
    // dump q (fp32, ld=68: multiple of 4 floats) into sB region; Wsr/bsr into sA
    float* qsm = (float*)sB;          // 64*68*4 = 17408 <= 2*64*72*2 = 18432 bytes
    float* swsr = (float*)sA;         // 2401+49 floats <= 4608 slots
    float* sbsr = swsr + 2401;
#pragma unroll
    for (int j = 0; j < 2; j++)
        wmma::store_matrix_sync(qsm + (mw * 16) * 68 + nw * 32 + j * 16, fc[j], 68, wmma::mem_row_major);
    for (int e = t; e < 2401; e += 256) swsr[e] = Wsr[e];
    if (t < CC) sbsr[t] = bsr[t];
    __syncthreads();
    // qW[c][j] = sum_p q[c][p]*Wsr[p][j]; padded zeros elsewhere
    for (int e = t; e < 4096; e += 256) {
        int c = e >> 6, j = e & 63;
        float s = 0.f;
        if (c < CC && j < CC) {
#pragma unroll
            for (int p = 0; p < CC; p++) s += qsm[c * 68 + p] * swsr[p * CC + j];
        }
        __nv_bfloat16 h, l; split1(s, h, l);
        g_qwh[b * 4096 + e] = h;
        g_qwl[b * 4096 + e] = l;
    }
    if (t < CC) {
        float s = 0.f;
#pragma unroll
        for (int p = 0; p < CC; p++) s += qsm[t * 68 + p] * sbsr[p];
        g_qb[b * CC + t] = s;
    }
}

// ---------------- kernel C: attn-max WMMA + fused v epilogue ----------------
// grid (B, 14), 224 thr. Stages x fp32 -> bf16 hi/lo in-register.
#define AM_ASTR 72
#define AM_BSTR 232
#define AM_ABYTES (2*64*AM_ASTR*2)            // 18432
#define AM_SMEM (AM_ABYTES + 2*64*AM_BSTR*2)  // + 59392 = 77824

__global__ __launch_bounds__(224) void k_amax_mma(const float* __restrict__ x) {
    extern __shared__ __align__(32) char smc[];
    __nv_bfloat16* sAh = (__nv_bfloat16*)smc;
    __nv_bfloat16* sAl = sAh + 64 * AM_ASTR;
    __nv_bfloat16* sBh = (__nv_bfloat16*)(smc + AM_ABYTES);
    __nv_bfloat16* sBl = sBh + 64 * AM_BSTR;
    __shared__ float swr[7][64];
    int b = blockIdx.x, ch = blockIdx.y;
    int t = threadIdx.x, w = t >> 5, lane = t & 31;
    int n0 = ch * 224;

    // stage A: padded qW hi/lo
    for (int e = t; e < 1024; e += 224) {
        int r = e >> 4, c4 = e & 15;
        *(uint2*)&sAh[r * AM_ASTR + c4 * 4] = ((const uint2*)(g_qwh + (size_t)b * 4096))[e];
        *(uint2*)&sAl[r * AM_ASTR + c4 * 4] = ((const uint2*)(g_qwl + (size_t)b * 4096))[e];
    }
    // stage B: x[j<49][n0..n0+223] fp32 -> hi/lo
    {
        const float* xb = x + (size_t)b * CC * NN + n0;
        for (int e = t; e < 2744; e += 224) {
            int r = e / 56, c4 = e - r * 56;
            float4 f = *(const float4*)(xb + (size_t)r * NN + c4 * 4);
            __nv_bfloat16 h0,l0,h1,l1,h2,l2,h3,l3;
            split1(f.x,h0,l0); split1(f.y,h1,l1); split1(f.z,h2,l2); split1(f.w,h3,l3);
            *(uint2*)&sBh[r * AM_BSTR + c4 * 4] = make_uint2(pk2(h0,h1), pk2(h2,h3));
            *(uint2*)&sBl[r * AM_BSTR + c4 * 4] = make_uint2(pk2(l0,l1), pk2(l2,l3));
        }
        // zero rows 49..63 (A pad is zero, but 0*NaN would poison)
        for (int e = t; e < 15 * 58; e += 224) {
            int r = CC + e / 58, c4 = e - (e / 58) * 58;
            *(uint2*)&sBh[r * AM_BSTR + c4 * 4] = make_uint2(0, 0);
            *(uint2*)&sBl[r * AM_BSTR + c4 * 4] = make_uint2(0, 0);
        }
    }
    __syncthreads();

    wmma::fragment<wmma::accumulator, 16, 16, 16, float> fc[2][4];
#pragma unroll
    for (int i = 0; i < 2; i++)
#pragma unroll
        for (int j = 0; j < 4; j++) wmma::fill_fragment(fc[i][j], 0.0f);

#pragma unroll
    for (int tile = 0; tile < 2; tile++) {
        int noff = (tile * 7 + w) * 16;
#pragma unroll
        for (int k4 = 0; k4 < 4; k4++) {
            wmma::fragment<wmma::matrix_b, 16, 16, 16, __nv_bfloat16, wmma::row_major> fbh, fbl;
            wmma::load_matrix_sync(fbh, &sBh[(k4 * 16) * AM_BSTR + noff], AM_BSTR);
            wmma::load_matrix_sync(fbl, &sBl[(k4 * 16) * AM_BSTR + noff], AM_BSTR);
#pragma unroll
            for (int band = 0; band < 4; band++) {
                wmma::fragment<wmma::matrix_a, 16, 16, 16, __nv_bfloat16, wmma::row_major> fah, fal;
                wmma::load_matrix_sync(fah, &sAh[(band * 16) * AM_ASTR + k4 * 16], AM_ASTR);
                wmma::load_matrix_sync(fal, &sAl[(band * 16) * AM_ASTR + k4 * 16], AM_ASTR);
                wmma::mma_sync(fc[tile][band], fah, fbh, fc[tile][band]);
                wmma::mma_sync(fc[tile][band], fal, fbh, fc[tile][band]);
                wmma::mma_sync(fc[tile][band], fah, fbl, fc[tile][band]);
            }
        }
    }
    __syncthreads();
    // fused v epilogue: v[b,n] = mean_j x[j][n] = mean over (hi+lo), then split
    {
        float s = 0.f;
#pragma unroll
        for (int j = 0; j < CC; j++)
            s += __bfloat162float(sBh[j * AM_BSTR + t]) + __bfloat162float(sBl[j * AM_BSTR + t]);
        s *= (1.0f / 49.0f);
        __nv_bfloat16 h, l; split1(s, h, l);
        g_vh[(size_t)b * NN + n0 + t] = h;
        g_vl[(size_t)b * NN + n0 + t] = l;
    }
    __syncthreads();
    // row-max epilogue (reuse B region as scratch: 7 warps x 4KB)
    float* sacc = (float*)sBh + w * 1024;
    float rm0 = -INFINITY, rm1 = -INFINITY;
#pragma unroll
    for (int tile = 0; tile < 2; tile++) {
#pragma unroll
        for (int band = 0; band < 4; band++)
            wmma::store_matrix_sync(sacc + band * 256, fc[tile][band], 16, wmma::mem_row_major);
        __syncwarp();
        {
            int r = lane;
            float m = sacc[r * 16];
#pragma unroll
            for (int c = 1; c < 16; c++) m = fmaxf(m, sacc[r * 16 + c]);
            rm0 = fmaxf(rm0, m);
            r = lane + 32;
            m = sacc[r * 16];
#pragma unroll
            for (int c = 1; c < 16; c++) m = fmaxf(m, sacc[r * 16 + c]);
            rm1 = fmaxf(rm1, m);
        }
        __syncwarp();
    }
    swr[w][lane] = rm0;
    swr[w][lane + 32] = rm1;
    __syncthreads();
    if (t < CC) {
        float m = swr[0][t];
#pragma unroll
        for (int w2 = 1; w2 < 7; w2++) m = fmaxf(m, swr[w2][t]);
        g_amax_part[(b * 14 + ch) * CC + t] = m;
    }
}

// ---------------- kernel D: s[m,b] WMMA, stage Wproj fp32 direct ------------
// grid (25, 7). 8 warps (4 mw x 2 nw). Tile 128m x 128b, K=448/split.
#define SG_STR 40
__global__ __launch_bounds__(256) void k_sgemm(const float* __restrict__ Wproj) {
    __shared__ __align__(32) __nv_bfloat16 sAh[128 * SG_STR], sAl[128 * SG_STR];
    __shared__ __align__(32) __nv_bfloat16 sBh[128 * SG_STR], sBl[128 * SG_STR];
    int m0 = blockIdx.x * 128, ks = blockIdx.y;
    int t = threadIdx.x, w = t >> 5;
    int mw = w & 3, nw = w >> 2;

    wmma::fragment<wmma::accumulator, 16, 16, 16, float> fc[2][4];
#pragma unroll
    for (int i = 0; i < 2; i++)
#pragma unroll
        for (int j = 0; j < 4; j++) wmma::fill_fragment(fc[i][j], 0.0f);

    for (int cch = 0; cch < 14; cch++) {
        int kb = ks * 448 + cch * 32;
        __syncthreads();
        // stage A: Wproj fp32 -> hi/lo (128 rows x 32 k)
        for (int e = t; e < 1024; e += 256) {
            int r = e >> 3, c4 = e & 7;
            int m = m0 + r;
            uint2 vh = make_uint2(0, 0), vl = make_uint2(0, 0);
            if (m < NN) {
                float4 f = *(const float4*)(Wproj + (size_t)m * NN + kb + c4 * 4);
                __nv_bfloat16 h0,l0,h1,l1,h2,l2,h3,l3;
                split1(f.x,h0,l0); split1(f.y,h1,l1); split1(f.z,h2,l2); split1(f.w,h3,l3);
                vh = make_uint2(pk2(h0,h1), pk2(h2,h3));
                vl = make_uint2(pk2(l0,l1), pk2(l2,l3));
            }
            *(uint2*)&sAh[r * SG_STR + c4 * 4] = vh;
            *(uint2*)&sAl[r * SG_STR + c4 * 4] = vl;
        }
        // stage B: v hi/lo (128 b-rows x 32 k)
        for (int e = t; e < 1024; e += 256) {
            int r = e >> 3, c4 = e & 7;
            *(uint2*)&sBh[r * SG_STR + c4 * 4] = *(const uint2*)(g_vh + (size_t)r * NN + kb + c4 * 4);
            *(uint2*)&sBl[r * SG_STR + c4 * 4] = *(const uint2*)(g_vl + (size_t)r * NN + kb + c4 * 4);
        }
        __syncthreads();
#pragma unroll
        for (int kstep = 0; kstep < 2; kstep++) {
            int k = kstep * 16;
            wmma::fragment<wmma::matrix_b, 16, 16, 16, __nv_bfloat16, wmma::col_major> fbh[4], fbl[4];
#pragma unroll
            for (int j = 0; j < 4; j++) {
                wmma::load_matrix_sync(fbh[j], &sBh[(nw * 64 + j * 16) * SG_STR + k], SG_STR);
                wmma::load_matrix_sync(fbl[j], &sBl[(nw * 64 + j * 16) * SG_STR + k], SG_STR);
            }
#pragma unroll
            for (int i = 0; i < 2; i++) {
                wmma::fragment<wmma::matrix_a, 16, 16, 16, __nv_bfloat16, wmma::row_major> fah, fal;
                wmma::load_matrix_sync(fah, &sAh[(mw * 32 + i * 16) * SG_STR + k], SG_STR);
                wmma::load_matrix_sync(fal, &sAl[(mw * 32 + i * 16) * SG_STR + k], SG_STR);
#pragma unroll
                for (int j = 0; j < 4; j++) {
                    wmma::mma_sync(fc[i][j], fah, fbh[j], fc[i][j]);
                    wmma::mma_sync(fc[i][j], fal, fbh[j], fc[i][j]);
                    wmma::mma_sync(fc[i][j], fah, fbl[j], fc[i][j]);
                }
            }
        }
    }
    float* dst = g_spart + (size_t)ks * (NN * BB);
#pragma unroll
    for (int i = 0; i < 2; i++) {
        int mrow = m0 + mw * 32 + i * 16;
        if (mrow < NN) {
#pragma unroll
            for (int j = 0; j < 4; j++)
                wmma::store_matrix_sync(dst + (size_t)mrow * BB + nw * 64 + j * 16,
                                        fc[i][j], BB, wmma::mem_row_major);
        }
    }
}

// ---------------- kernel E: final max over 14 chunks + qb -------------------
__global__ void k_amax2() {
    int idx = blockIdx.x * blockDim.x + threadIdx.x;
    if (idx >= BB * CC) return;
    int b = idx / CC, c = idx - b * CC;
    float m = -INFINITY;
#pragma unroll
    for (int ch = 0; ch < 14; ch++) m = fmaxf(m, g_amax_part[(b * 14 + ch) * CC + c]);
    g_amax[idx] = m + g_qb[idx];
}

// ---------------- kernel F: out[b,m,c] = amax[b,c] * sum_ks spart[ks][m,b] --
__global__ void k_out(float* __restrict__ out) {
    __shared__ float sa[CC];
    __shared__ float ss[64];
    int b = blockIdx.x, mt = blockIdx.y, t = threadIdx.x;  // 256 threads
    if (t < CC) sa[t] = g_amax[b * CC + t];
    if (t < 64) {
        int m = mt * 64 + t;
        float s = 0.f;
#pragma unroll
        for (int ks = 0; ks < 7; ks++) s += g_spart[(size_t)ks * NN * BB + m * BB + b];
        ss[t] = s;
    }
    __syncthreads();
    float* ob = out + ((size_t)b * NN + mt * 64) * CC;
    for (int e = t; e < 64 * CC; e += 256) {
        int m = e / CC, c = e - m * CC;
        ob[e] = ss[m] * sa[c];
    }
}

// ---------------- launch -----------------------------------------------------
extern "C" void kernel_launch(void* const* d_in, const int* in_sizes, int n_in,
                              void* d_out, int out_size) {
    const float *x = nullptr, *Wq = nullptr, *Wsr = nullptr, *bsr = nullptr, *Wproj = nullptr;
    for (int i = 0; i < n_in; i++) {
        switch (in_sizes[i]) {
            case BB * CC * NN: x     = (const float*)d_in[i]; break;
            case CC * CC * 64: Wq    = (const float*)d_in[i]; break;
            case CC * CC:      Wsr   = (const float*)d_in[i]; break;
            case CC:           bsr   = (const float*)d_in[i]; break;
            case NN * NN:      Wproj = (const float*)d_in[i]; break;
            default: break;
        }
    }
    cudaFuncSetAttribute(k_amax_mma, cudaFuncAttributeMaxDynamicSharedMemorySize, AM_SMEM);

    k_wqsplit  <<<(64 * NN + 255) / 256, 256>>>(Wq);            // 1
    k_qconv_mma<<<BB, 256>>>(x, Wsr, bsr);                      // 2
    k_amax_mma <<<dim3(BB, 14), 224, AM_SMEM>>>(x);             // 3
    k_sgemm    <<<dim3(25, 7), 256>>>(Wproj);                   // 4 <- profiled
    k_amax2    <<<(BB * CC + 255) / 256, 256>>>();              // 5
    k_out      <<<dim3(BB, NN / 64), 256>>>((float*)d_out);     // 6
}

// round 10
// speedup vs baseline: 1.7482x; 1.4349x over previous
#include <cuda_runtime.h>
#include <cuda_bf16.h>
#include <mma.h>
#include <math.h>
#include <stdint.h>

using namespace nvcuda;

#define BB 128
#define CC 49
#define NN 3136
#define HH 56

// ---------------- scratch (device globals; no allocations allowed) ----------
__device__ float g_qb[BB*CC];                   // qb[b][c]
__device__ float g_qpart[7*BB*4096];            // channel-group partials of q
__device__ float g_amax_part[BB*14*CC];         // per-chunk maxima
__device__ float g_amax[BB*CC];                 // final max + qb
__device__ float g_spart[14*NN*BB];             // k-split partials of s[m][b]
__device__ __nv_bfloat16 g_vh[BB*NN];           // v hi
__device__ __nv_bfloat16 g_vl[BB*NN];           // v lo
__device__ __nv_bfloat16 g_wqh[64*NN];          // Wq_mat hi [o<64][i*64+k], rows>=49 zero
__device__ __nv_bfloat16 g_wql[64*NN];          // Wq_mat lo
__device__ __nv_bfloat16 g_qwh[BB*64*64];       // qW hi padded [b][c<64][j<64], pad zero
__device__ __nv_bfloat16 g_qwl[BB*64*64];       // qW lo padded

__device__ __forceinline__ uint32_t pk2(__nv_bfloat16 a, __nv_bfloat16 b) {
    __nv_bfloat162 t2; t2.x = a; t2.y = b;
    return *reinterpret_cast<uint32_t*>(&t2);
}
__device__ __forceinline__ void split1(float f, __nv_bfloat16& h, __nv_bfloat16& l) {
    h = __float2bfloat16(f);
    l = __float2bfloat16(f - __bfloat162float(h));
}

// ---------------- kernel A: Wq -> padded bf16 hi/lo matrix ------------------
__global__ void k_wqsplit(const float* __restrict__ Wq) {
    int e = blockIdx.x * blockDim.x + threadIdx.x;   // over 64*3136
    if (e >= 64 * NN) return;
    int r = e / NN, c = e - r * NN;
    float f = (r < CC) ? Wq[r * NN + c] : 0.f;       // Wq is [49][49*64] linear
    __nv_bfloat16 h, l; split1(f, h, l);
    g_wqh[e] = h; g_wql[e] = l;
}

// ---------------- kernel B: q conv partials, grid (B, 7) --------------------
// Each block: 7 channels of the K reduction; partial q[64,64] -> g_qpart.
#define QC_ASTR 72
#define QC_BSTR 72
__global__ __launch_bounds__(256) void k_qconv_part(const float* __restrict__ x) {
    __shared__ __align__(32) __nv_bfloat16 sA[2 * 64 * QC_ASTR];  // hi | lo
    __shared__ __align__(32) __nv_bfloat16 sB[2 * 64 * QC_BSTR];  // hi | lo
    __nv_bfloat16* sAh = sA; __nv_bfloat16* sAl = sA + 64 * QC_ASTR;
    __nv_bfloat16* sBh = sB; __nv_bfloat16* sBl = sB + 64 * QC_BSTR;
    int b = blockIdx.x, g = blockIdx.y;
    int t = threadIdx.x, w = t >> 5;
    int mw = w & 3, nw = w >> 2;      // 4 m-tiles x 2 n-halves(32)

    wmma::fragment<wmma::accumulator, 16, 16, 16, float> fc[2];
    wmma::fill_fragment(fc[0], 0.0f);
    wmma::fill_fragment(fc[1], 0.0f);

    // one-time zero of B (pad columns p in [49,72) stay zero)
    for (int e = t; e < 2 * 64 * QC_BSTR; e += 256) sB[e] = __float2bfloat16(0.f);

    for (int ii = 0; ii < 7; ii++) {
        int i = g * 7 + ii;
        __syncthreads();
        // stage B: channel image -> im2col [k=64][p<49], bf16 hi/lo split
        const float* xc = x + ((size_t)b * CC + i) * NN;
        for (int e = t; e < NN; e += 256) {
            int h = e / HH, ww = e - h * HH;
            int k = (h & 7) * 8 + (ww & 7);
            int p = (h >> 3) * 7 + (ww >> 3);
            __nv_bfloat16 hh, ll; split1(xc[e], hh, ll);
            sBh[k * QC_BSTR + p] = hh;
            sBl[k * QC_BSTR + p] = ll;
        }
        // stage A: Wq_mat rows, k-chunk for channel i (uint2 = 4 bf16)
        for (int e = t; e < 1024; e += 256) {
            int r = e >> 4, c4 = e & 15;
            *(uint2*)&sAh[r * QC_ASTR + c4 * 4] = ((const uint2*)g_wqh)[r * 784 + i * 16 + c4];
            *(uint2*)&sAl[r * QC_ASTR + c4 * 4] = ((const uint2*)g_wql)[r * 784 + i * 16 + c4];
        }
        __syncthreads();
#pragma unroll
        for (int k4 = 0; k4 < 4; k4++) {
            wmma::fragment<wmma::matrix_a, 16, 16, 16, __nv_bfloat16, wmma::row_major> fah, fal;
            wmma::load_matrix_sync(fah, &sAh[(mw * 16) * QC_ASTR + k4 * 16], QC_ASTR);
            wmma::load_matrix_sync(fal, &sAl[(mw * 16) * QC_ASTR + k4 * 16], QC_ASTR);
#pragma unroll
            for (int j = 0; j < 2; j++) {
                wmma::fragment<wmma::matrix_b, 16, 16, 16, __nv_bfloat16, wmma::row_major> fbh, fbl;
                wmma::load_matrix_sync(fbh, &sBh[(k4 * 16) * QC_BSTR + nw * 32 + j * 16], QC_BSTR);
                wmma::load_matrix_sync(fbl, &sBl[(k4 * 16) * QC_BSTR + nw * 32 + j * 16], QC_BSTR);
                wmma::mma_sync(fc[j], fah, fbh, fc[j]);
                wmma::mma_sync(fc[j], fal, fbh, fc[j]);
                wmma::mma_sync(fc[j], fah, fbl, fc[j]);
            }
        }
    }
    float* dst = g_qpart + (size_t)(b * 7 + g) * 4096;
#pragma unroll
    for (int j = 0; j < 2; j++)
        wmma::store_matrix_sync(dst + (mw * 16) * 64 + nw * 32 + j * 16, fc[j], 64, wmma::mem_row_major);
}

// ---------------- kernel B2: reduce q partials + qW/qb epilogue -------------
__global__ __launch_bounds__(256) void k_qreduce(const float* __restrict__ Wsr,
                                                 const float* __restrict__ bsr) {
    __shared__ float qsm[64 * 64];
    __shared__ float swsr[CC * CC];
    __shared__ float sbsr[CC];
    int b = blockIdx.x, t = threadIdx.x;
    for (int e = t; e < 4096; e += 256) {
        float s = 0.f;
#pragma unroll
        for (int g = 0; g < 7; g++) s += g_qpart[(size_t)(b * 7 + g) * 4096 + e];
        qsm[e] = s;
    }
    for (int e = t; e < CC * CC; e += 256) swsr[e] = Wsr[e];
    if (t < CC) sbsr[t] = bsr[t];
    __syncthreads();
    for (int e = t; e < 4096; e += 256) {
        int c = e >> 6, j = e & 63;
        float s = 0.f;
        if (c < CC && j < CC) {
#pragma unroll
            for (int p = 0; p < CC; p++) s += qsm[c * 64 + p] * swsr[p * CC + j];
        }
        __nv_bfloat16 h, l; split1(s, h, l);
        g_qwh[b * 4096 + e] = h;
        g_qwl[b * 4096 + e] = l;
    }
    if (t < CC) {
        float s = 0.f;
#pragma unroll
        for (int p = 0; p < CC; p++) s += qsm[t * 64 + p] * sbsr[p];
        g_qb[b * CC + t] = s;
    }
}

// ---------------- kernel C: attn-max WMMA + fused v epilogue ----------------
// grid (B, 14), 224 thr. Stages x fp32 -> bf16 hi/lo in-register.
#define AM_ASTR 72
#define AM_BSTR 232
#define AM_ABYTES (2*64*AM_ASTR*2)            // 18432
#define AM_SMEM (AM_ABYTES + 2*64*AM_BSTR*2)  // + 59392 = 77824

__global__ __launch_bounds__(224) void k_amax_mma(const float* __restrict__ x) {
    extern __shared__ __align__(32) char smc[];
    __nv_bfloat16* sAh = (__nv_bfloat16*)smc;
    __nv_bfloat16* sAl = sAh + 64 * AM_ASTR;
    __nv_bfloat16* sBh = (__nv_bfloat16*)(smc + AM_ABYTES);
    __nv_bfloat16* sBl = sBh + 64 * AM_BSTR;
    __shared__ float swr[7][64];
    int b = blockIdx.x, ch = blockIdx.y;
    int t = threadIdx.x, w = t >> 5, lane = t & 31;
    int n0 = ch * 224;

    // stage A: padded qW hi/lo
    for (int e = t; e < 1024; e += 224) {
        int r = e >> 4, c4 = e & 15;
        *(uint2*)&sAh[r * AM_ASTR + c4 * 4] = ((const uint2*)(g_qwh + (size_t)b * 4096))[e];
        *(uint2*)&sAl[r * AM_ASTR + c4 * 4] = ((const uint2*)(g_qwl + (size_t)b * 4096))[e];
    }
    // stage B: x[j<49][n0..n0+223] fp32 -> hi/lo
    {
        const float* xb = x + (size_t)b * CC * NN + n0;
        for (int e = t; e < 2744; e += 224) {
            int r = e / 56, c4 = e - r * 56;
            float4 f = *(const float4*)(xb + (size_t)r * NN + c4 * 4);
            __nv_bfloat16 h0,l0,h1,l1,h2,l2,h3,l3;
            split1(f.x,h0,l0); split1(f.y,h1,l1); split1(f.z,h2,l2); split1(f.w,h3,l3);
            *(uint2*)&sBh[r * AM_BSTR + c4 * 4] = make_uint2(pk2(h0,h1), pk2(h2,h3));
            *(uint2*)&sBl[r * AM_BSTR + c4 * 4] = make_uint2(pk2(l0,l1), pk2(l2,l3));
        }
        // zero rows 49..63 (A pad is zero, but 0*NaN would poison)
        for (int e = t; e < 15 * 58; e += 224) {
            int r = CC + e / 58, c4 = e - (e / 58) * 58;
            *(uint2*)&sBh[r * AM_BSTR + c4 * 4] = make_uint2(0, 0);
            *(uint2*)&sBl[r * AM_BSTR + c4 * 4] = make_uint2(0, 0);
        }
    }
    __syncthreads();

    wmma::fragment<wmma::accumulator, 16, 16, 16, float> fc[2][4];
#pragma unroll
    for (int i = 0; i < 2; i++)
#pragma unroll
        for (int j = 0; j < 4; j++) wmma::fill_fragment(fc[i][j], 0.0f);

#pragma unroll
    for (int tile = 0; tile < 2; tile++) {
        int noff = (tile * 7 + w) * 16;
#pragma unroll
        for (int k4 = 0; k4 < 4; k4++) {
            wmma::fragment<wmma::matrix_b, 16, 16, 16, __nv_bfloat16, wmma::row_major> fbh, fbl;
            wmma::load_matrix_sync(fbh, &sBh[(k4 * 16) * AM_BSTR + noff], AM_BSTR);
            wmma::load_matrix_sync(fbl, &sBl[(k4 * 16) * AM_BSTR + noff], AM_BSTR);
#pragma unroll
            for (int band = 0; band < 4; band++) {
                wmma::fragment<wmma::matrix_a, 16, 16, 16, __nv_bfloat16, wmma::row_major> fah, fal;
                wmma::load_matrix_sync(fah, &sAh[(band * 16) * AM_ASTR + k4 * 16], AM_ASTR);
                wmma::load_matrix_sync(fal, &sAl[(band * 16) * AM_ASTR + k4 * 16], AM_ASTR);
                wmma::mma_sync(fc[tile][band], fah, fbh, fc[tile][band]);
                wmma::mma_sync(fc[tile][band], fal, fbh, fc[tile][band]);
                wmma::mma_sync(fc[tile][band], fah, fbl, fc[tile][band]);
            }
        }
    }
    __syncthreads();
    // fused v epilogue: v[b,n] = mean_j x[j][n] = mean over (hi+lo), then split
    {
        float s = 0.f;
#pragma unroll
        for (int j = 0; j < CC; j++)
            s += __bfloat162float(sBh[j * AM_BSTR + t]) + __bfloat162float(sBl[j * AM_BSTR + t]);
        s *= (1.0f / 49.0f);
        __nv_bfloat16 h, l; split1(s, h, l);
        g_vh[(size_t)b * NN + n0 + t] = h;
        g_vl[(size_t)b * NN + n0 + t] = l;
    }
    __syncthreads();
    // row-max epilogue (reuse B region as scratch: 7 warps x 4KB)
    float* sacc = (float*)sBh + w * 1024;
    float rm0 = -INFINITY, rm1 = -INFINITY;
#pragma unroll
    for (int tile = 0; tile < 2; tile++) {
#pragma unroll
        for (int band = 0; band < 4; band++)
            wmma::store_matrix_sync(sacc + band * 256, fc[tile][band], 16, wmma::mem_row_major);
        __syncwarp();
        {
            int r = lane;
            float m = sacc[r * 16];
#pragma unroll
            for (int c = 1; c < 16; c++) m = fmaxf(m, sacc[r * 16 + c]);
            rm0 = fmaxf(rm0, m);
            r = lane + 32;
            m = sacc[r * 16];
#pragma unroll
            for (int c = 1; c < 16; c++) m = fmaxf(m, sacc[r * 16 + c]);
            rm1 = fmaxf(rm1, m);
        }
        __syncwarp();
    }
    swr[w][lane] = rm0;
    swr[w][lane + 32] = rm1;
    __syncthreads();
    if (t < CC) {
        float m = swr[0][t];
#pragma unroll
        for (int w2 = 1; w2 < 7; w2++) m = fmaxf(m, swr[w2][t]);
        g_amax_part[(b * 14 + ch) * CC + t] = m;
    }
}

// ---------------- kernel D: s[m,b] WMMA, k-split 14, 2 blocks/SM ------------
// grid (25, 14). 8 warps (4 mw x 2 nw). Tile 128m x 128b, K=224/split.
#define SG_STR 40
__global__ __launch_bounds__(256, 2) void k_sgemm(const float* __restrict__ Wproj) {
    __shared__ __align__(32) __nv_bfloat16 sAh[128 * SG_STR], sAl[128 * SG_STR];
    __shared__ __align__(32) __nv_bfloat16 sBh[128 * SG_STR], sBl[128 * SG_STR];
    int m0 = blockIdx.x * 128, ks = blockIdx.y;
    int t = threadIdx.x, w = t >> 5;
    int mw = w & 3, nw = w >> 2;

    wmma::fragment<wmma::accumulator, 16, 16, 16, float> fc[2][4];
#pragma unroll
    for (int i = 0; i < 2; i++)
#pragma unroll
        for (int j = 0; j < 4; j++) wmma::fill_fragment(fc[i][j], 0.0f);

    for (int cch = 0; cch < 7; cch++) {
        int kb = ks * 224 + cch * 32;
        __syncthreads();
        // stage A: Wproj fp32 -> hi/lo (128 rows x 32 k)
        for (int e = t; e < 1024; e += 256) {
            int r = e >> 3, c4 = e & 7;
            int m = m0 + r;
            uint2 vh = make_uint2(0, 0), vl = make_uint2(0, 0);
            if (m < NN) {
                float4 f = *(const float4*)(Wproj + (size_t)m * NN + kb + c4 * 4);
                __nv_bfloat16 h0,l0,h1,l1,h2,l2,h3,l3;
                split1(f.x,h0,l0); split1(f.y,h1,l1); split1(f.z,h2,l2); split1(f.w,h3,l3);
                vh = make_uint2(pk2(h0,h1), pk2(h2,h3));
                vl = make_uint2(pk2(l0,l1), pk2(l2,l3));
            }
            *(uint2*)&sAh[r * SG_STR + c4 * 4] = vh;
            *(uint2*)&sAl[r * SG_STR + c4 * 4] = vl;
        }
        // stage B: v hi/lo (128 b-rows x 32 k)
        for (int e = t; e < 1024; e += 256) {
            int r = e >> 3, c4 = e & 7;
            *(uint2*)&sBh[r * SG_STR + c4 * 4] = *(const uint2*)(g_vh + (size_t)r * NN + kb + c4 * 4);
            *(uint2*)&sBl[r * SG_STR + c4 * 4] = *(const uint2*)(g_vl + (size_t)r * NN + kb + c4 * 4);
        }
        __syncthreads();
#pragma unroll
        for (int kstep = 0; kstep < 2; kstep++) {
            int k = kstep * 16;
#pragma unroll
            for (int j = 0; j < 4; j++) {
                wmma::fragment<wmma::matrix_b, 16, 16, 16, __nv_bfloat16, wmma::col_major> fbh, fbl;
                wmma::load_matrix_sync(fbh, &sBh[(nw * 64 + j * 16) * SG_STR + k], SG_STR);
                wmma::load_matrix_sync(fbl, &sBl[(nw * 64 + j * 16) * SG_STR + k], SG_STR);
#pragma unroll
                for (int i = 0; i < 2; i++) {
                    wmma::fragment<wmma::matrix_a, 16, 16, 16, __nv_bfloat16, wmma::row_major> fah, fal;
                    wmma::load_matrix_sync(fah, &sAh[(mw * 32 + i * 16) * SG_STR + k], SG_STR);
                    wmma::load_matrix_sync(fal, &sAl[(mw * 32 + i * 16) * SG_STR + k], SG_STR);
                    wmma::mma_sync(fc[i][j], fah, fbh, fc[i][j]);
                    wmma::mma_sync(fc[i][j], fal, fbh, fc[i][j]);
                    wmma::mma_sync(fc[i][j], fah, fbl, fc[i][j]);
                }
            }
        }
    }
    float* dst = g_spart + (size_t)ks * (NN * BB);
#pragma unroll
    for (int i = 0; i < 2; i++) {
        int mrow = m0 + mw * 32 + i * 16;
        if (mrow < NN) {
#pragma unroll
            for (int j = 0; j < 4; j++)
                wmma::store_matrix_sync(dst + (size_t)mrow * BB + nw * 64 + j * 16,
                                        fc[i][j], BB, wmma::mem_row_major);
        }
    }
}

// ---------------- kernel E: final max over 14 chunks + qb -------------------
__global__ void k_amax2() {
    int idx = blockIdx.x * blockDim.x + threadIdx.x;
    if (idx >= BB * CC) return;
    int b = idx / CC, c = idx - b * CC;
    float m = -INFINITY;
#pragma unroll
    for (int ch = 0; ch < 14; ch++) m = fmaxf(m, g_amax_part[(b * 14 + ch) * CC + c]);
    g_amax[idx] = m + g_qb[idx];
}

// ---------------- kernel F: out[b,m,c] = amax[b,c] * sum_ks spart[ks][m,b] --
__global__ void k_out(float* __restrict__ out) {
    __shared__ float sa[CC];
    __shared__ float ss[64];
    int b = blockIdx.x, mt = blockIdx.y, t = threadIdx.x;  // 256 threads
    if (t < CC) sa[t] = g_amax[b * CC + t];
    if (t < 64) {
        int m = mt * 64 + t;
        float s = 0.f;
#pragma unroll
        for (int ks = 0; ks < 14; ks++) s += g_spart[(size_t)ks * NN * BB + m * BB + b];
        ss[t] = s;
    }
    __syncthreads();
    float* ob = out + ((size_t)b * NN + mt * 64) * CC;
    for (int e = t; e < 64 * CC; e += 256) {
        int m = e / CC, c = e - m * CC;
        ob[e] = ss[m] * sa[c];
    }
}

// ---------------- launch -----------------------------------------------------
extern "C" void kernel_launch(void* const* d_in, const int* in_sizes, int n_in,
                              void* d_out, int out_size) {
    const float *x = nullptr, *Wq = nullptr, *Wsr = nullptr, *bsr = nullptr, *Wproj = nullptr;
    for (int i = 0; i < n_in; i++) {
        switch (in_sizes[i]) {
            case BB * CC * NN: x     = (const float*)d_in[i]; break;
            case CC * CC * 64: Wq    = (const float*)d_in[i]; break;
            case CC * CC:      Wsr   = (const float*)d_in[i]; break;
            case CC:           bsr   = (const float*)d_in[i]; break;
            case NN * NN:      Wproj = (const float*)d_in[i]; break;
            default: break;
        }
    }
    cudaFuncSetAttribute(k_amax_mma, cudaFuncAttributeMaxDynamicSharedMemorySize, AM_SMEM);

    k_wqsplit   <<<(64 * NN + 255) / 256, 256>>>(Wq);           // 1
    k_qconv_part<<<dim3(BB, 7), 256>>>(x);                      // 2
    k_qreduce   <<<BB, 256>>>(Wsr, bsr);                        // 3
    k_amax_mma  <<<dim3(BB, 14), 224, AM_SMEM>>>(x);            // 4 <- profiled
    k_sgemm     <<<dim3(25, 14), 256>>>(Wproj);                 // 5
    k_amax2     <<<(BB * CC + 255) / 256, 256>>>();             // 6
    k_out       <<<dim3(BB, NN / 64), 256>>>((float*)d_out);    // 7
}

// round 11
// speedup vs baseline: 2.3189x; 1.3265x over previous
#include <cuda_runtime.h>
#include <cuda_bf16.h>
#include <mma.h>
#include <math.h>
#include <stdint.h>

using namespace nvcuda;

#define BB 128
#define CC 49
#define NN 3136
#define HH 56

// ---------------- scratch (device globals; no allocations allowed) ----------
__device__ float g_qb[BB*CC];                   // qb[b][c]
__device__ float g_qpart[7*BB*4096];            // channel-group partials of q
__device__ float g_amax_part[BB*28*CC];         // per-chunk maxima
__device__ float g_amax[BB*CC];                 // final max + qb
__device__ float g_spart[14*NN*BB];             // k-split partials of s[m][b]
__device__ __nv_bfloat16 g_vh[BB*NN];           // v hi
__device__ __nv_bfloat16 g_vl[BB*NN];           // v lo
__device__ __nv_bfloat16 g_wqh[64*NN];          // Wq_mat hi [o<64][i*64+k], rows>=49 zero
__device__ __nv_bfloat16 g_wql[64*NN];          // Wq_mat lo
__device__ __nv_bfloat16 g_qwh[BB*64*64];       // qW hi padded [b][c<64][j<64], pad zero
__device__ __nv_bfloat16 g_qwl[BB*64*64];       // qW lo padded

__device__ __forceinline__ uint32_t pk2(__nv_bfloat16 a, __nv_bfloat16 b) {
    __nv_bfloat162 t2; t2.x = a; t2.y = b;
    return *reinterpret_cast<uint32_t*>(&t2);
}
__device__ __forceinline__ void split1(float f, __nv_bfloat16& h, __nv_bfloat16& l) {
    h = __float2bfloat16(f);
    l = __float2bfloat16(f - __bfloat162float(h));
}

// ---------------- kernel A: Wq -> padded bf16 hi/lo matrix ------------------
__global__ void k_wqsplit(const float* __restrict__ Wq) {
    int e = blockIdx.x * blockDim.x + threadIdx.x;   // over 64*3136
    if (e >= 64 * NN) return;
    int r = e / NN, c = e - r * NN;
    float f = (r < CC) ? Wq[r * NN + c] : 0.f;       // Wq is [49][49*64] linear
    __nv_bfloat16 h, l; split1(f, h, l);
    g_wqh[e] = h; g_wql[e] = l;
}

// ---------------- kernel B: q conv partials, grid (B, 7) --------------------
// Each block: 7 channels of the K reduction; partial q[64,64] -> g_qpart.
#define QC_ASTR 72
#define QC_BSTR 72
__global__ __launch_bounds__(256) void k_qconv_part(const float* __restrict__ x) {
    __shared__ __align__(32) __nv_bfloat16 sA[2 * 64 * QC_ASTR];  // hi | lo
    __shared__ __align__(32) __nv_bfloat16 sB[2 * 64 * QC_BSTR];  // hi | lo
    __nv_bfloat16* sAh = sA; __nv_bfloat16* sAl = sA + 64 * QC_ASTR;
    __nv_bfloat16* sBh = sB; __nv_bfloat16* sBl = sB + 64 * QC_BSTR;
    int b = blockIdx.x, g = blockIdx.y;
    int t = threadIdx.x, w = t >> 5;
    int mw = w & 3, nw = w >> 2;      // 4 m-tiles x 2 n-halves(32)

    wmma::fragment<wmma::accumulator, 16, 16, 16, float> fc[2];
    wmma::fill_fragment(fc[0], 0.0f);
    wmma::fill_fragment(fc[1], 0.0f);

    // one-time zero of B (pad columns p in [49,72) stay zero)
    for (int e = t; e < 2 * 64 * QC_BSTR; e += 256) sB[e] = __float2bfloat16(0.f);

    for (int ii = 0; ii < 7; ii++) {
        int i = g * 7 + ii;
        __syncthreads();
        // stage B: channel image -> im2col [k=64][p<49], bf16 hi/lo split
        const float* xc = x + ((size_t)b * CC + i) * NN;
        for (int e = t; e < NN; e += 256) {
            int h = e / HH, ww = e - h * HH;
            int k = (h & 7) * 8 + (ww & 7);
            int p = (h >> 3) * 7 + (ww >> 3);
            __nv_bfloat16 hh, ll; split1(xc[e], hh, ll);
            sBh[k * QC_BSTR + p] = hh;
            sBl[k * QC_BSTR + p] = ll;
        }
        // stage A: Wq_mat rows, k-chunk for channel i (uint2 = 4 bf16)
        for (int e = t; e < 1024; e += 256) {
            int r = e >> 4, c4 = e & 15;
            *(uint2*)&sAh[r * QC_ASTR + c4 * 4] = ((const uint2*)g_wqh)[r * 784 + i * 16 + c4];
            *(uint2*)&sAl[r * QC_ASTR + c4 * 4] = ((const uint2*)g_wql)[r * 784 + i * 16 + c4];
        }
        __syncthreads();
#pragma unroll
        for (int k4 = 0; k4 < 4; k4++) {
            wmma::fragment<wmma::matrix_a, 16, 16, 16, __nv_bfloat16, wmma::row_major> fah, fal;
            wmma::load_matrix_sync(fah, &sAh[(mw * 16) * QC_ASTR + k4 * 16], QC_ASTR);
            wmma::load_matrix_sync(fal, &sAl[(mw * 16) * QC_ASTR + k4 * 16], QC_ASTR);
#pragma unroll
            for (int j = 0; j < 2; j++) {
                wmma::fragment<wmma::matrix_b, 16, 16, 16, __nv_bfloat16, wmma::row_major> fbh, fbl;
                wmma::load_matrix_sync(fbh, &sBh[(k4 * 16) * QC_BSTR + nw * 32 + j * 16], QC_BSTR);
                wmma::load_matrix_sync(fbl, &sBl[(k4 * 16) * QC_BSTR + nw * 32 + j * 16], QC_BSTR);
                wmma::mma_sync(fc[j], fah, fbh, fc[j]);
                wmma::mma_sync(fc[j], fal, fbh, fc[j]);
                wmma::mma_sync(fc[j], fah, fbl, fc[j]);
            }
        }
    }
    float* dst = g_qpart + (size_t)(b * 7 + g) * 4096;
#pragma unroll
    for (int j = 0; j < 2; j++)
        wmma::store_matrix_sync(dst + (mw * 16) * 64 + nw * 32 + j * 16, fc[j], 64, wmma::mem_row_major);
}

// ---------------- kernel B2: reduce q partials + qW/qb epilogue -------------
__global__ __launch_bounds__(256) void k_qreduce(const float* __restrict__ Wsr,
                                                 const float* __restrict__ bsr) {
    __shared__ float qsm[64 * 64];
    __shared__ float swsr[CC * CC];
    __shared__ float sbsr[CC];
    int b = blockIdx.x, t = threadIdx.x;
    for (int e = t; e < 4096; e += 256) {
        float s = 0.f;
#pragma unroll
        for (int g = 0; g < 7; g++) s += g_qpart[(size_t)(b * 7 + g) * 4096 + e];
        qsm[e] = s;
    }
    for (int e = t; e < CC * CC; e += 256) swsr[e] = Wsr[e];
    if (t < CC) sbsr[t] = bsr[t];
    __syncthreads();
    for (int e = t; e < 4096; e += 256) {
        int c = e >> 6, j = e & 63;
        float s = 0.f;
        if (c < CC && j < CC) {
#pragma unroll
            for (int p = 0; p < CC; p++) s += qsm[c * 64 + p] * swsr[p * CC + j];
        }
        __nv_bfloat16 h, l; split1(s, h, l);
        g_qwh[b * 4096 + e] = h;
        g_qwl[b * 4096 + e] = l;
    }
    if (t < CC) {
        float s = 0.f;
#pragma unroll
        for (int p = 0; p < CC; p++) s += qsm[t * 64 + p] * sbsr[p];
        g_qb[b * CC + t] = s;
    }
}

// ---------------- kernel C: attn-max WMMA + fused v epilogue ----------------
// grid (B, 28), 224 thr. n-chunk 112; warp w owns n-tile w (16 cols), 4 bands.
#define AM_ASTR 72
#define AM_BSTR 120
#define AM_ABYTES (2*64*AM_ASTR*2)            // 18432
#define AM_SMEM (AM_ABYTES + 2*64*AM_BSTR*2)  // + 30720 = 49152

__global__ __launch_bounds__(224, 3) void k_amax_mma(const float* __restrict__ x) {
    extern __shared__ __align__(32) char smc[];
    __nv_bfloat16* sAh = (__nv_bfloat16*)smc;
    __nv_bfloat16* sAl = sAh + 64 * AM_ASTR;
    __nv_bfloat16* sBh = (__nv_bfloat16*)(smc + AM_ABYTES);
    __nv_bfloat16* sBl = sBh + 64 * AM_BSTR;
    __shared__ float swr[7][64];
    int b = blockIdx.x, ch = blockIdx.y;
    int t = threadIdx.x, w = t >> 5, lane = t & 31;
    int n0 = ch * 112;

    // stage A: padded qW hi/lo
    for (int e = t; e < 1024; e += 224) {
        int r = e >> 4, c4 = e & 15;
        *(uint2*)&sAh[r * AM_ASTR + c4 * 4] = ((const uint2*)(g_qwh + (size_t)b * 4096))[e];
        *(uint2*)&sAl[r * AM_ASTR + c4 * 4] = ((const uint2*)(g_qwl + (size_t)b * 4096))[e];
    }
    // stage B: x[j<49][n0..n0+111] fp32 -> hi/lo (28 uint2 groups per row)
    {
        const float* xb = x + (size_t)b * CC * NN + n0;
        for (int e = t; e < 1372; e += 224) {
            int r = e / 28, c4 = e - r * 28;
            float4 f = *(const float4*)(xb + (size_t)r * NN + c4 * 4);
            __nv_bfloat16 h0,l0,h1,l1,h2,l2,h3,l3;
            split1(f.x,h0,l0); split1(f.y,h1,l1); split1(f.z,h2,l2); split1(f.w,h3,l3);
            *(uint2*)&sBh[r * AM_BSTR + c4 * 4] = make_uint2(pk2(h0,h1), pk2(h2,h3));
            *(uint2*)&sBl[r * AM_BSTR + c4 * 4] = make_uint2(pk2(l0,l1), pk2(l2,l3));
        }
        // zero rows 49..63 (30 uint2 groups per 120-wide row)
        for (int e = t; e < 15 * 30; e += 224) {
            int r = CC + e / 30, c4 = e - (e / 30) * 30;
            *(uint2*)&sBh[r * AM_BSTR + c4 * 4] = make_uint2(0, 0);
            *(uint2*)&sBl[r * AM_BSTR + c4 * 4] = make_uint2(0, 0);
        }
    }
    __syncthreads();

    wmma::fragment<wmma::accumulator, 16, 16, 16, float> fc[4];
#pragma unroll
    for (int j = 0; j < 4; j++) wmma::fill_fragment(fc[j], 0.0f);

    int noff = w * 16;
#pragma unroll
    for (int k4 = 0; k4 < 4; k4++) {
        wmma::fragment<wmma::matrix_b, 16, 16, 16, __nv_bfloat16, wmma::row_major> fbh, fbl;
        wmma::load_matrix_sync(fbh, &sBh[(k4 * 16) * AM_BSTR + noff], AM_BSTR);
        wmma::load_matrix_sync(fbl, &sBl[(k4 * 16) * AM_BSTR + noff], AM_BSTR);
#pragma unroll
        for (int band = 0; band < 4; band++) {
            wmma::fragment<wmma::matrix_a, 16, 16, 16, __nv_bfloat16, wmma::row_major> fah, fal;
            wmma::load_matrix_sync(fah, &sAh[(band * 16) * AM_ASTR + k4 * 16], AM_ASTR);
            wmma::load_matrix_sync(fal, &sAl[(band * 16) * AM_ASTR + k4 * 16], AM_ASTR);
            wmma::mma_sync(fc[band], fah, fbh, fc[band]);
            wmma::mma_sync(fc[band], fal, fbh, fc[band]);
            wmma::mma_sync(fc[band], fah, fbl, fc[band]);
        }
    }
    __syncthreads();
    // fused v epilogue: v[b,n] = mean_j x[j][n] over (hi+lo), then split
    if (t < 112) {
        float s = 0.f;
#pragma unroll
        for (int j = 0; j < CC; j++)
            s += __bfloat162float(sBh[j * AM_BSTR + t]) + __bfloat162float(sBl[j * AM_BSTR + t]);
        s *= (1.0f / 49.0f);
        __nv_bfloat16 h, l; split1(s, h, l);
        g_vh[(size_t)b * NN + n0 + t] = h;
        g_vl[(size_t)b * NN + n0 + t] = l;
    }
    __syncthreads();
    // row-max epilogue (reuse B region as scratch: 7 warps x 4KB)
    float* sacc = (float*)sBh + w * 1024;
#pragma unroll
    for (int band = 0; band < 4; band++)
        wmma::store_matrix_sync(sacc + band * 256, fc[band], 16, wmma::mem_row_major);
    __syncwarp();
    {
        int r = lane;
        float m = sacc[r * 16];
#pragma unroll
        for (int c = 1; c < 16; c++) m = fmaxf(m, sacc[r * 16 + c]);
        swr[w][lane] = m;
        r = lane + 32;
        m = sacc[r * 16];
#pragma unroll
        for (int c = 1; c < 16; c++) m = fmaxf(m, sacc[r * 16 + c]);
        swr[w][lane + 32] = m;
    }
    __syncthreads();
    if (t < CC) {
        float m = swr[0][t];
#pragma unroll
        for (int w2 = 1; w2 < 7; w2++) m = fmaxf(m, swr[w2][t]);
        g_amax_part[(b * 28 + ch) * CC + t] = m;
    }
}

// ---------------- kernel D: s[m,b] WMMA, tile 64m x 128b, k-split 14 --------
// grid (49, 14). 8 warps (4 mw x 2 nw); warp = 16m x 64b. K=224/split.
#define SG_STR 40
__global__ __launch_bounds__(256, 3) void k_sgemm(const float* __restrict__ Wproj) {
    __shared__ __align__(32) __nv_bfloat16 sAh[64 * SG_STR], sAl[64 * SG_STR];
    __shared__ __align__(32) __nv_bfloat16 sBh[128 * SG_STR], sBl[128 * SG_STR];
    int m0 = blockIdx.x * 64, ks = blockIdx.y;
    int t = threadIdx.x, w = t >> 5;
    int mw = w & 3, nw = w >> 2;

    wmma::fragment<wmma::accumulator, 16, 16, 16, float> fc[4];
#pragma unroll
    for (int j = 0; j < 4; j++) wmma::fill_fragment(fc[j], 0.0f);

    for (int cch = 0; cch < 7; cch++) {
        int kb = ks * 224 + cch * 32;
        __syncthreads();
        // stage A: Wproj fp32 -> hi/lo (64 rows x 32 k); 49*64=3136 exact, no bounds
        for (int e = t; e < 512; e += 256) {
            int r = e >> 3, c4 = e & 7;
            float4 f = *(const float4*)(Wproj + (size_t)(m0 + r) * NN + kb + c4 * 4);
            __nv_bfloat16 h0,l0,h1,l1,h2,l2,h3,l3;
            split1(f.x,h0,l0); split1(f.y,h1,l1); split1(f.z,h2,l2); split1(f.w,h3,l3);
            *(uint2*)&sAh[r * SG_STR + c4 * 4] = make_uint2(pk2(h0,h1), pk2(h2,h3));
            *(uint2*)&sAl[r * SG_STR + c4 * 4] = make_uint2(pk2(l0,l1), pk2(l2,l3));
        }
        // stage B: v hi/lo (128 b-rows x 32 k)
        for (int e = t; e < 1024; e += 256) {
            int r = e >> 3, c4 = e & 7;
            *(uint2*)&sBh[r * SG_STR + c4 * 4] = *(const uint2*)(g_vh + (size_t)r * NN + kb + c4 * 4);
            *(uint2*)&sBl[r * SG_STR + c4 * 4] = *(const uint2*)(g_vl + (size_t)r * NN + kb + c4 * 4);
        }
        __syncthreads();
#pragma unroll
        for (int kstep = 0; kstep < 2; kstep++) {
            int k = kstep * 16;
            wmma::fragment<wmma::matrix_a, 16, 16, 16, __nv_bfloat16, wmma::row_major> fah, fal;
            wmma::load_matrix_sync(fah, &sAh[(mw * 16) * SG_STR + k], SG_STR);
            wmma::load_matrix_sync(fal, &sAl[(mw * 16) * SG_STR + k], SG_STR);
#pragma unroll
            for (int j = 0; j < 4; j++) {
                wmma::fragment<wmma::matrix_b, 16, 16, 16, __nv_bfloat16, wmma::col_major> fbh, fbl;
                wmma::load_matrix_sync(fbh, &sBh[(nw * 64 + j * 16) * SG_STR + k], SG_STR);
                wmma::load_matrix_sync(fbl, &sBl[(nw * 64 + j * 16) * SG_STR + k], SG_STR);
                wmma::mma_sync(fc[j], fah, fbh, fc[j]);
                wmma::mma_sync(fc[j], fal, fbh, fc[j]);
                wmma::mma_sync(fc[j], fah, fbl, fc[j]);
            }
        }
    }
    float* dst = g_spart + (size_t)ks * (NN * BB) + (size_t)(m0 + mw * 16) * BB;
#pragma unroll
    for (int j = 0; j < 4; j++)
        wmma::store_matrix_sync(dst + nw * 64 + j * 16, fc[j], BB, wmma::mem_row_major);
}

// ---------------- kernel E: final max over 28 chunks + qb -------------------
__global__ void k_amax2() {
    int idx = blockIdx.x * blockDim.x + threadIdx.x;
    if (idx >= BB * CC) return;
    int b = idx / CC, c = idx - b * CC;
    float m = -INFINITY;
#pragma unroll
    for (int ch = 0; ch < 28; ch++) m = fmaxf(m, g_amax_part[(b * 28 + ch) * CC + c]);
    g_amax[idx] = m + g_qb[idx];
}

// ---------------- kernel F: out[b,m,c] = amax[b,c] * sum_ks spart[ks][m,b] --
__global__ void k_out(float* __restrict__ out) {
    __shared__ float sa[CC];
    __shared__ float ss[64];
    int b = blockIdx.x, mt = blockIdx.y, t = threadIdx.x;  // 256 threads
    if (t < CC) sa[t] = g_amax[b * CC + t];
    if (t < 64) {
        int m = mt * 64 + t;
        float s = 0.f;
#pragma unroll
        for (int ks = 0; ks < 14; ks++) s += g_spart[(size_t)ks * NN * BB + m * BB + b];
        ss[t] = s;
    }
    __syncthreads();
    float* ob = out + ((size_t)b * NN + mt * 64) * CC;
    for (int e = t; e < 64 * CC; e += 256) {
        int m = e / CC, c = e - m * CC;
        ob[e] = ss[m] * sa[c];
    }
}

// ---------------- launch -----------------------------------------------------
extern "C" void kernel_launch(void* const* d_in, const int* in_sizes, int n_in,
                              void* d_out, int out_size) {
    const float *x = nullptr, *Wq = nullptr, *Wsr = nullptr, *bsr = nullptr, *Wproj = nullptr;
    for (int i = 0; i < n_in; i++) {
        switch (in_sizes[i]) {
            case BB * CC * NN: x     = (const float*)d_in[i]; break;
            case CC * CC * 64: Wq    = (const float*)d_in[i]; break;
            case CC * CC:      Wsr   = (const float*)d_in[i]; break;
            case CC:           bsr   = (const float*)d_in[i]; break;
            case NN * NN:      Wproj = (const float*)d_in[i]; break;
            default: break;
        }
    }
    cudaFuncSetAttribute(k_amax_mma, cudaFuncAttributeMaxDynamicSharedMemorySize, AM_SMEM);

    k_wqsplit   <<<(64 * NN + 255) / 256, 256>>>(Wq);           // 1
    k_qconv_part<<<dim3(BB, 7), 256>>>(x);                      // 2
    k_qreduce   <<<BB, 256>>>(Wsr, bsr);                        // 3
    k_amax_mma  <<<dim3(BB, 28), 224, AM_SMEM>>>(x);            // 4 <- profiled
    k_sgemm     <<<dim3(49, 14), 256>>>(Wproj);                 // 5
    k_amax2     <<<(BB * CC + 255) / 256, 256>>>();             // 6
    k_out       <<<dim3(BB, NN / 64), 256>>>((float*)d_out);    // 7
}